// round 16
// baseline (speedup 1.0000x reference)
#include <cuda_runtime.h>
#include <cuda_bf16.h>
#include <math.h>
#include <stdint.h>

#define QLEN 900
#define DM   256
#define NH   8
#define HD   32
#define NPTS 4
#define FFD  1024

// ---------------- scratch (__device__ globals; allocation-free) ----------------
__device__ float g_t1[1843200];
__device__ float g_val[20480000];     // [B*HW, 256]
__device__ float g_proj[1843200];
__device__ float g_t2[1843200];
__device__ float g_dproj[921600];     // [B*Q, 128] deform projections
__device__ float g_dbias[128];
// bf16 hi/lo split buffers
__device__ __nv_bfloat16 g_ah[20480000];   // branch A (memory) exclusive
__device__ __nv_bfloat16 g_al[20480000];
__device__ __nv_bfloat16 g_bh[1843200];    // branch B activations
__device__ __nv_bfloat16 g_bl[1843200];
__device__ __nv_bfloat16 g_wh[917504];     // all weights concatenated
__device__ __nv_bfloat16 g_wl[917504];
__device__ __nv_bfloat16 g_ch[32768];      // deform proj weights 128x256
__device__ __nv_bfloat16 g_cl[32768];
__device__ __nv_bfloat16 g_fh[7372800];    // qkv / ffn intermediate hi
__device__ __nv_bfloat16 g_fl[7372800];    // qkv / ffn intermediate lo

// ============================================================================
// helpers
// ============================================================================
__device__ __forceinline__ uint32_t smem_u32(const void* p) {
    uint32_t a;
    asm("{ .reg .u64 t; cvta.to.shared.u64 t, %1; cvt.u32.u64 %0, t; }"
        : "=r"(a) : "l"(p));
    return a;
}
__device__ __forceinline__ uint32_t sw64(uint32_t off) {
    return off ^ ((off >> 3) & 0x30);
}
__device__ __forceinline__ void cvt_split(float f, uint16_t& h, uint16_t& l) {
    __nv_bfloat16 hb = __float2bfloat16_rn(f);
    float r = f - __bfloat162float(hb);
    __nv_bfloat16 lb = __float2bfloat16_rn(r);
    h = *reinterpret_cast<uint16_t*>(&hb);
    l = *reinterpret_cast<uint16_t*>(&lb);
}
__device__ __forceinline__ void ldmx4(uint32_t* r, uint32_t addr) {
    asm volatile("ldmatrix.sync.aligned.m8n8.x4.shared.b16 {%0,%1,%2,%3}, [%4];"
        : "=r"(r[0]), "=r"(r[1]), "=r"(r[2]), "=r"(r[3]) : "r"(addr));
}
__device__ __forceinline__ void ldmx4t(uint32_t* r, uint32_t addr) {
    asm volatile("ldmatrix.sync.aligned.m8n8.x4.trans.shared.b16 {%0,%1,%2,%3}, [%4];"
        : "=r"(r[0]), "=r"(r[1]), "=r"(r[2]), "=r"(r[3]) : "r"(addr));
}
__device__ __forceinline__ void mma16816(float* d, const uint32_t* a,
                                         uint32_t b0, uint32_t b1) {
    asm volatile(
        "mma.sync.aligned.m16n8k16.row.col.f32.bf16.bf16.f32 "
        "{%0,%1,%2,%3}, {%4,%5,%6,%7}, {%8,%9}, {%0,%1,%2,%3};"
        : "+f"(d[0]), "+f"(d[1]), "+f"(d[2]), "+f"(d[3])
        : "r"(a[0]), "r"(a[1]), "r"(a[2]), "r"(a[3]), "r"(b0), "r"(b1));
}
__device__ __forceinline__ void cp_async16(uint32_t dst, const void* src, uint32_t sz) {
    asm volatile("cp.async.cg.shared.global [%0], [%1], 16, %2;"
        :: "r"(dst), "l"(src), "r"(sz));
}
#define CP_COMMIT() asm volatile("cp.async.commit_group;" ::: "memory")
#define CP_WAIT0()  asm volatile("cp.async.wait_group 0;" ::: "memory")
#define CP_WAIT1()  asm volatile("cp.async.wait_group 1;" ::: "memory")

// ============================================================================
// split_bf16: fp32 -> (hi, lo) bf16; 8 elems (2 float4 in, uint4 out) / thread.
// ============================================================================
__global__ __launch_bounds__(256) void split_bf16(
    const float* __restrict__ x, __nv_bfloat16* __restrict__ hi,
    __nv_bfloat16* __restrict__ lo, int n8)
{
    int i = blockIdx.x * 256 + threadIdx.x;
    if (i >= n8) return;
    float4 v0 = ((const float4*)x)[2 * i];
    float4 v1 = ((const float4*)x)[2 * i + 1];
    uint16_t h[8], l[8];
    cvt_split(v0.x, h[0], l[0]); cvt_split(v0.y, h[1], l[1]);
    cvt_split(v0.z, h[2], l[2]); cvt_split(v0.w, h[3], l[3]);
    cvt_split(v1.x, h[4], l[4]); cvt_split(v1.y, h[5], l[5]);
    cvt_split(v1.z, h[6], l[6]); cvt_split(v1.w, h[7], l[7]);
    ((uint4*)hi)[i] = make_uint4(
        (uint32_t)h[0] | ((uint32_t)h[1] << 16), (uint32_t)h[2] | ((uint32_t)h[3] << 16),
        (uint32_t)h[4] | ((uint32_t)h[5] << 16), (uint32_t)h[6] | ((uint32_t)h[7] << 16));
    ((uint4*)lo)[i] = make_uint4(
        (uint32_t)l[0] | ((uint32_t)l[1] << 16), (uint32_t)l[2] | ((uint32_t)l[3] << 16),
        (uint32_t)l[4] | ((uint32_t)l[5] << 16), (uint32_t)l[6] | ((uint32_t)l[7] << 16));
}

// ============================================================================
// split_weights: all 6 weight matrices -> one concatenated hi/lo buffer.
// ============================================================================
__global__ __launch_bounds__(256) void split_weights(
    const float* __restrict__ vpw, const float* __restrict__ inw,
    const float* __restrict__ outw, const float* __restrict__ cow,
    const float* __restrict__ f1w, const float* __restrict__ f2w,
    __nv_bfloat16* __restrict__ wh, __nv_bfloat16* __restrict__ wl)
{
    int i0 = blockIdx.x * 1024 + threadIdx.x;
#pragma unroll
    for (int it = 0; it < 4; it++) {
        int i = i0 + it * 256;
        if (i >= 229376) return;
        const float* src; int li;
        if (i < 16384)       { src = vpw;  li = i; }
        else if (i < 65536)  { src = inw;  li = i - 16384; }
        else if (i < 81920)  { src = outw; li = i - 65536; }
        else if (i < 98304)  { src = cow;  li = i - 81920; }
        else if (i < 163840) { src = f1w;  li = i - 98304; }
        else                 { src = f2w;  li = i - 163840; }
        float4 v = ((const float4*)src)[li];
        uint16_t h0,h1,h2,h3,l0,l1,l2,l3;
        cvt_split(v.x,h0,l0); cvt_split(v.y,h1,l1);
        cvt_split(v.z,h2,l2); cvt_split(v.w,h3,l3);
        ((uint2*)wh)[i] = make_uint2((uint32_t)h0 | ((uint32_t)h1 << 16),
                                     (uint32_t)h2 | ((uint32_t)h3 << 16));
        ((uint2*)wl)[i] = make_uint2((uint32_t)l0 | ((uint32_t)l1 << 16),
                                     (uint32_t)l2 | ((uint32_t)l3 << 16));
    }
}

// ============================================================================
// build_dproj_w: concat [ref(2) | offs(64) | attw(32) | pad(30)] x 256 weights
// ============================================================================
__global__ __launch_bounds__(256) void build_dproj_w(
    const float* __restrict__ rfw, const float* __restrict__ rfb,
    const float* __restrict__ ofw, const float* __restrict__ ofb,
    const float* __restrict__ aww, const float* __restrict__ awb,
    __nv_bfloat16* __restrict__ ch, __nv_bfloat16* __restrict__ cl,
    float* __restrict__ dbias)
{
    int row = blockIdx.x, tid = threadIdx.x;
    float v = 0.f;
    if (row < 2)       v = rfw[row * 256 + tid];
    else if (row < 66) v = ofw[(row - 2) * 256 + tid];
    else if (row < 98) v = aww[(row - 66) * 256 + tid];
    uint16_t hh, ll;
    cvt_split(v, hh, ll);
    *(uint16_t*)(ch + row * 256 + tid) = hh;
    *(uint16_t*)(cl + row * 256 + tid) = ll;
    if (tid == 0)
        dbias[row] = row < 2 ? rfb[row] : row < 66 ? ofb[row - 2]
                   : row < 98 ? awb[row - 66] : 0.f;
}

// ============================================================================
// hgemm: C = act(A @ W^T + bias), bf16x3.
// 4 warps (128 thr), 2x2 warp grid of 64x64 sub-tiles.
// BK=32, 2-stage cp.async, 64KB smem, 2 CTAs/SM.
// ============================================================================
#define HG_SMEM (2 * 32768)

__global__ __launch_bounds__(128, 2) void hgemm(
    const __nv_bfloat16* __restrict__ Ah, const __nv_bfloat16* __restrict__ Al,
    const __nv_bfloat16* __restrict__ Wh, const __nv_bfloat16* __restrict__ Wl,
    const float* __restrict__ bias, float* __restrict__ C,
    __nv_bfloat16* __restrict__ Ch, __nv_bfloat16* __restrict__ Cl,
    int M, int N, int K, int mode)
{
    extern __shared__ char sm[];
    const uint32_t sb = smem_u32(sm);
    const int tid = threadIdx.x;
    const int wid = tid >> 5, lane = tid & 31;
    const int row0 = blockIdx.y * 128, col0 = blockIdx.x * 128;
    const int wm = (wid & 1) * 64;
    const int wn = (wid >> 1) * 64;

    float acc[4][8][4];
#pragma unroll
    for (int mt = 0; mt < 4; mt++)
#pragma unroll
        for (int nt = 0; nt < 8; nt++)
#pragma unroll
            for (int j = 0; j < 4; j++) acc[mt][nt][j] = 0.f;

    const uint32_t a_row = wm + (lane & 15);
    const uint32_t a_cb  = (lane >> 4) * 16;
    const uint32_t b_rowb = wn + (lane & 7) + ((lane >> 4) << 3);
    const uint32_t b_cb  = ((lane >> 3) & 1) * 16;
    const int nc = K >> 5;                 // chunks of 32

    auto load_chunk = [&](int c, uint32_t bufbase) {
        const int k0 = c << 5;
#pragma unroll
        for (int it = 0; it < 4; it++) {
            int slot = tid + it * 128;
            int r = slot >> 2;
            int le8 = (slot & 3) * 8;
            uint32_t so = sw64((uint32_t)(r * 64 + le8 * 2));
            int ra = row0 + r < M ? row0 + r : M - 1;
            uint32_t asz = (row0 + r < M) ? 16u : 0u;
            cp_async16(bufbase + so,         Ah + (size_t)ra * K + k0 + le8, asz);
            cp_async16(bufbase + 8192 + so,  Al + (size_t)ra * K + k0 + le8, asz);
            cp_async16(bufbase + 16384 + so, Wh + (size_t)(col0 + r) * K + k0 + le8, 16u);
            cp_async16(bufbase + 24576 + so, Wl + (size_t)(col0 + r) * K + k0 + le8, 16u);
        }
    };

    load_chunk(0, sb);
    CP_COMMIT();

    for (int c = 0; c < nc; c++) {
        const uint32_t stb = sb + (uint32_t)(c & 1) * 32768;
        if (c + 1 < nc) {
            load_chunk(c + 1, sb + (uint32_t)((c + 1) & 1) * 32768);
            CP_COMMIT();
            CP_WAIT1();
        } else {
            CP_WAIT0();
        }
        __syncthreads();

#pragma unroll
        for (int ks = 0; ks < 32; ks += 16) {
            uint32_t ah[4][4], alr[4][4];
#pragma unroll
            for (int mt = 0; mt < 4; mt++) {
                uint32_t off = sw64((a_row + mt * 16) * 64 + ks * 2 + a_cb);
                ldmx4(ah[mt],  stb + off);
                ldmx4(alr[mt], stb + 8192 + off);
            }
#pragma unroll
            for (int jj = 0; jj < 4; jj++) {
                uint32_t off = sw64((b_rowb + jj * 16) * 64 + ks * 2 + b_cb);
                uint32_t bhh[4], bll[4];
                ldmx4(bhh, stb + 16384 + off);
                ldmx4(bll, stb + 24576 + off);
#pragma unroll
                for (int mt = 0; mt < 4; mt++) {
                    mma16816(acc[mt][2*jj],   ah[mt], bhh[0], bhh[1]);
                    mma16816(acc[mt][2*jj+1], ah[mt], bhh[2], bhh[3]);
                }
#pragma unroll
                for (int mt = 0; mt < 4; mt++) {
                    mma16816(acc[mt][2*jj],   ah[mt], bll[0], bll[1]);
                    mma16816(acc[mt][2*jj+1], ah[mt], bll[2], bll[3]);
                }
#pragma unroll
                for (int mt = 0; mt < 4; mt++) {
                    mma16816(acc[mt][2*jj],   alr[mt], bhh[0], bhh[1]);
                    mma16816(acc[mt][2*jj+1], alr[mt], bhh[2], bhh[3]);
                }
            }
        }
        __syncthreads();
    }

    const bool relu = mode & 1;
    const bool split = mode & 2;
#pragma unroll
    for (int mt = 0; mt < 4; mt++) {
        int r0e = row0 + wm + mt * 16 + (lane >> 2);
#pragma unroll
        for (int nt = 0; nt < 8; nt++) {
            int c = col0 + wn + nt * 8 + (lane & 3) * 2;
            float b0 = bias[c], b1 = bias[c + 1];
            float2 v0 = make_float2(acc[mt][nt][0] + b0, acc[mt][nt][1] + b1);
            float2 v1 = make_float2(acc[mt][nt][2] + b0, acc[mt][nt][3] + b1);
            if (relu) {
                v0.x = fmaxf(v0.x, 0.f); v0.y = fmaxf(v0.y, 0.f);
                v1.x = fmaxf(v1.x, 0.f); v1.y = fmaxf(v1.y, 0.f);
            }
            if (!split) {
                if (r0e < M)     *(float2*)(C + (size_t)r0e * N + c) = v0;
                if (r0e + 8 < M) *(float2*)(C + (size_t)(r0e + 8) * N + c) = v1;
            } else {
                uint16_t h0,h1,l0,l1;
                if (r0e < M) {
                    cvt_split(v0.x, h0, l0); cvt_split(v0.y, h1, l1);
                    *(uint32_t*)(Ch + (size_t)r0e * N + c) =
                        (uint32_t)h0 | ((uint32_t)h1 << 16);
                    *(uint32_t*)(Cl + (size_t)r0e * N + c) =
                        (uint32_t)l0 | ((uint32_t)l1 << 16);
                }
                if (r0e + 8 < M) {
                    cvt_split(v1.x, h0, l0); cvt_split(v1.y, h1, l1);
                    *(uint32_t*)(Ch + (size_t)(r0e + 8) * N + c) =
                        (uint32_t)h0 | ((uint32_t)h1 << 16);
                    *(uint32_t*)(Cl + (size_t)(r0e + 8) * N + c) =
                        (uint32_t)l0 | ((uint32_t)l1 << 16);
                }
            }
        }
    }
}

// ============================================================================
// flash_mma: fused flash self-attention, bf16x3, split-bf16 QKV inputs.
// 128-query tiles, 256 threads (8 warps x 16 rows): halves K/V re-reads.
// ============================================================================
__global__ __launch_bounds__(256) void flash_mma(
    const __nv_bfloat16* __restrict__ QKVh, const __nv_bfloat16* __restrict__ QKVl,
    __nv_bfloat16* __restrict__ Oh, __nv_bfloat16* __restrict__ Ol)
{
    __shared__ __align__(16) char sQ[2][8192];       // [hi/lo] 128 rows x 64B
    __shared__ __align__(16) char sKV[2][4][4096];   // [stage][Kh,Kl,Vh,Vl]

    const int bh = blockIdx.y;
    const int b = bh >> 3, h = bh & 7;
    const int q0 = blockIdx.x * 128;
    const int tid = threadIdx.x;
    const int w = tid >> 5, lane = tid & 31;
    const float scale = 0.17677669529663687f;

    const size_t rowbase = (size_t)b * QLEN * 768 + h * 32;
    const __nv_bfloat16* gqh = QKVh + rowbase;
    const __nv_bfloat16* gql = QKVl + rowbase;

    const uint32_t uQ0 = smem_u32(sQ[0]), uQ1 = smem_u32(sQ[1]);
    const uint32_t uKV = smem_u32(sKV[0][0]);

    // Q load: 256 thr cover 128 rows x 2 half-rows
    const int qrow = tid >> 1;
    const int qel  = (tid & 1) * 16;
    // KV load: 256 thr cover 64 rows x 4 quarter-rows (1 cp per region)
    const int krow = tid >> 2;
    const int kel  = (tid & 3) * 8;
    const uint32_t kso = sw64((uint32_t)(krow * 64 + kel * 2));

    {
        uint32_t qsz = (q0 + qrow < QLEN) ? 16u : 0u;
        const __nv_bfloat16* sh = gqh + (size_t)(q0 + qrow) * 768 + qel;
        const __nv_bfloat16* sl = gql + (size_t)(q0 + qrow) * 768 + qel;
        uint32_t qo0 = sw64((uint32_t)(qrow * 64 + qel * 2));
        uint32_t qo1 = sw64((uint32_t)(qrow * 64 + qel * 2 + 16));
        cp_async16(uQ0 + qo0, sh, qsz);     cp_async16(uQ0 + qo1, sh + 8, qsz);
        cp_async16(uQ1 + qo0, sl, qsz);     cp_async16(uQ1 + qo1, sl + 8, qsz);
        uint32_t ksz = (krow < QLEN) ? 16u : 0u;   // k0 = 0
        cp_async16(uKV + kso,         gqh + 256 + (size_t)krow * 768 + kel, ksz);
        cp_async16(uKV + 4096 + kso,  gql + 256 + (size_t)krow * 768 + kel, ksz);
        cp_async16(uKV + 8192 + kso,  gqh + 512 + (size_t)krow * 768 + kel, ksz);
        cp_async16(uKV + 12288 + kso, gql + 512 + (size_t)krow * 768 + kel, ksz);
        CP_COMMIT();
    }
    CP_WAIT0();
    __syncthreads();

    uint32_t qa[2][2][4];
#pragma unroll
    for (int ks = 0; ks < 2; ks++) {
        uint32_t off = sw64((uint32_t)((w*16 + (lane & 15)) * 64
                            + ks * 32 + (lane >> 4) * 16));
        ldmx4(qa[0][ks], uQ0 + off);
        ldmx4(qa[1][ks], uQ1 + off);
    }

    float m0 = -1e30f, m1 = -1e30f, l0s = 0.f, l1s = 0.f;
    float o[4][4];
#pragma unroll
    for (int i = 0; i < 4; i++)
#pragma unroll
        for (int j = 0; j < 4; j++) o[i][j] = 0.f;

    for (int kt = 0; kt < 15; kt++) {
        if (kt < 14) {
            const int k0n = (kt + 1) * 64;
            const uint32_t nb = uKV + (uint32_t)((kt + 1) & 1) * 16384;
            uint32_t ksz = (k0n + krow < QLEN) ? 16u : 0u;
            cp_async16(nb + kso,         gqh + 256 + (size_t)(k0n + krow) * 768 + kel, ksz);
            cp_async16(nb + 4096 + kso,  gql + 256 + (size_t)(k0n + krow) * 768 + kel, ksz);
            cp_async16(nb + 8192 + kso,  gqh + 512 + (size_t)(k0n + krow) * 768 + kel, ksz);
            cp_async16(nb + 12288 + kso, gql + 512 + (size_t)(k0n + krow) * 768 + kel, ksz);
            CP_COMMIT();
        }

        const uint32_t stb = uKV + (uint32_t)(kt & 1) * 16384;
        const int k0 = kt * 64;

        float s[8][4];
#pragma unroll
        for (int i = 0; i < 8; i++)
#pragma unroll
            for (int j = 0; j < 4; j++) s[i][j] = 0.f;
#pragma unroll
        for (int ks = 0; ks < 2; ks++) {
            uint32_t bhh[4][4], bll[4][4];
#pragma unroll
            for (int jj = 0; jj < 4; jj++) {
                uint32_t off = sw64((uint32_t)((jj*16 + (lane & 7)
                               + ((lane >> 4) << 3)) * 64
                               + ((lane >> 3) & 1) * 16 + ks * 32));
                ldmx4(bhh[jj], stb + off);
                ldmx4(bll[jj], stb + 4096 + off);
            }
#pragma unroll
            for (int jj = 0; jj < 4; jj++) {
                mma16816(s[2*jj],   qa[0][ks], bhh[jj][0], bhh[jj][1]);
                mma16816(s[2*jj+1], qa[0][ks], bhh[jj][2], bhh[jj][3]);
            }
#pragma unroll
            for (int jj = 0; jj < 4; jj++) {
                mma16816(s[2*jj],   qa[0][ks], bll[jj][0], bll[jj][1]);
                mma16816(s[2*jj+1], qa[0][ks], bll[jj][2], bll[jj][3]);
            }
#pragma unroll
            for (int jj = 0; jj < 4; jj++) {
                mma16816(s[2*jj],   qa[1][ks], bhh[jj][0], bhh[jj][1]);
                mma16816(s[2*jj+1], qa[1][ks], bhh[jj][2], bhh[jj][3]);
            }
        }
#pragma unroll
        for (int jn = 0; jn < 8; jn++) {
#pragma unroll
            for (int j = 0; j < 4; j++) s[jn][j] *= scale;
        }
        const int colb = k0 + (lane & 3) * 2;
#pragma unroll
        for (int jn = 0; jn < 8; jn++) {
            int c0 = colb + jn * 8;
            if (c0 >= QLEN)     { s[jn][0] = -1e30f; s[jn][2] = -1e30f; }
            if (c0 + 1 >= QLEN) { s[jn][1] = -1e30f; s[jn][3] = -1e30f; }
        }

        float mx0 = -1e30f, mx1 = -1e30f;
#pragma unroll
        for (int jn = 0; jn < 8; jn++) {
            mx0 = fmaxf(mx0, fmaxf(s[jn][0], s[jn][1]));
            mx1 = fmaxf(mx1, fmaxf(s[jn][2], s[jn][3]));
        }
        mx0 = fmaxf(mx0, __shfl_xor_sync(0xffffffffu, mx0, 1));
        mx0 = fmaxf(mx0, __shfl_xor_sync(0xffffffffu, mx0, 2));
        mx1 = fmaxf(mx1, __shfl_xor_sync(0xffffffffu, mx1, 1));
        mx1 = fmaxf(mx1, __shfl_xor_sync(0xffffffffu, mx1, 2));
        float mn0 = fmaxf(m0, mx0), mn1 = fmaxf(m1, mx1);
        float corr0 = __expf(m0 - mn0), corr1 = __expf(m1 - mn1);
        m0 = mn0; m1 = mn1;
        float rs0 = 0.f, rs1 = 0.f;
#pragma unroll
        for (int jn = 0; jn < 8; jn++) {
            s[jn][0] = __expf(s[jn][0] - mn0);
            s[jn][1] = __expf(s[jn][1] - mn0);
            s[jn][2] = __expf(s[jn][2] - mn1);
            s[jn][3] = __expf(s[jn][3] - mn1);
            rs0 += s[jn][0] + s[jn][1];
            rs1 += s[jn][2] + s[jn][3];
        }
        rs0 += __shfl_xor_sync(0xffffffffu, rs0, 1);
        rs0 += __shfl_xor_sync(0xffffffffu, rs0, 2);
        rs1 += __shfl_xor_sync(0xffffffffu, rs1, 1);
        rs1 += __shfl_xor_sync(0xffffffffu, rs1, 2);
        l0s = l0s * corr0 + rs0;
        l1s = l1s * corr1 + rs1;
#pragma unroll
        for (int jn = 0; jn < 4; jn++) {
            o[jn][0] *= corr0; o[jn][1] *= corr0;
            o[jn][2] *= corr1; o[jn][3] *= corr1;
        }

#pragma unroll
        for (int ks = 0; ks < 4; ks++) {
            uint32_t pah[4], pal[4];
            {
                const float* t0 = s[2*ks];
                const float* t1 = s[2*ks+1];
                uint16_t h0,h1,l0,l1;
                cvt_split(t0[0],h0,l0); cvt_split(t0[1],h1,l1);
                pah[0] = (uint32_t)h0 | ((uint32_t)h1<<16);
                pal[0] = (uint32_t)l0 | ((uint32_t)l1<<16);
                cvt_split(t0[2],h0,l0); cvt_split(t0[3],h1,l1);
                pah[1] = (uint32_t)h0 | ((uint32_t)h1<<16);
                pal[1] = (uint32_t)l0 | ((uint32_t)l1<<16);
                cvt_split(t1[0],h0,l0); cvt_split(t1[1],h1,l1);
                pah[2] = (uint32_t)h0 | ((uint32_t)h1<<16);
                pal[2] = (uint32_t)l0 | ((uint32_t)l1<<16);
                cvt_split(t1[2],h0,l0); cvt_split(t1[3],h1,l1);
                pah[3] = (uint32_t)h0 | ((uint32_t)h1<<16);
                pal[3] = (uint32_t)l0 | ((uint32_t)l1<<16);
            }
            uint32_t vrow = (uint32_t)(ks * 16 + (lane & 7) + ((lane >> 3) & 1) * 8);
            uint32_t vhh[2][4], vll[2][4];
#pragma unroll
            for (int jj = 0; jj < 2; jj++) {
                uint32_t off = sw64(vrow * 64 + jj * 32 + (lane >> 4) * 16);
                ldmx4t(vhh[jj], stb + 8192 + off);
                ldmx4t(vll[jj], stb + 12288 + off);
            }
#pragma unroll
            for (int jj = 0; jj < 2; jj++) {
                mma16816(o[2*jj],   pah, vhh[jj][0], vhh[jj][1]);
                mma16816(o[2*jj+1], pah, vhh[jj][2], vhh[jj][3]);
            }
#pragma unroll
            for (int jj = 0; jj < 2; jj++) {
                mma16816(o[2*jj],   pah, vll[jj][0], vll[jj][1]);
                mma16816(o[2*jj+1], pah, vll[jj][2], vll[jj][3]);
            }
#pragma unroll
            for (int jj = 0; jj < 2; jj++) {
                mma16816(o[2*jj],   pal, vhh[jj][0], vhh[jj][1]);
                mma16816(o[2*jj+1], pal, vhh[jj][2], vhh[jj][3]);
            }
        }

        if (kt < 14) CP_WAIT0();
        __syncthreads();
    }

    {
        int r0 = q0 + w * 16 + (lane >> 2);
        float i0 = 1.f / l0s, i1 = 1.f / l1s;
#pragma unroll
        for (int jn = 0; jn < 4; jn++) {
            int c = h * 32 + jn * 8 + (lane & 3) * 2;
            uint16_t h0,h1,l0,l1;
            if (r0 < QLEN) {
                cvt_split(o[jn][0] * i0, h0, l0);
                cvt_split(o[jn][1] * i0, h1, l1);
                size_t off = (size_t)(b * QLEN + r0) * 256 + c;
                *(uint32_t*)(Oh + off) = (uint32_t)h0 | ((uint32_t)h1 << 16);
                *(uint32_t*)(Ol + off) = (uint32_t)l0 | ((uint32_t)l1 << 16);
            }
            if (r0 + 8 < QLEN) {
                cvt_split(o[jn][2] * i1, h0, l0);
                cvt_split(o[jn][3] * i1, h1, l1);
                size_t off = (size_t)(b * QLEN + r0 + 8) * 256 + c;
                *(uint32_t*)(Oh + off) = (uint32_t)h0 | ((uint32_t)h1 << 16);
                *(uint32_t*)(Ol + off) = (uint32_t)l0 | ((uint32_t)l1 << 16);
            }
        }
    }
}

// ---------------------------------------------------------------------------
// out = LayerNorm(a + b); optionally also emits bf16 hi/lo split of out.
// ---------------------------------------------------------------------------
__global__ __launch_bounds__(256) void add_ln(
    const float* __restrict__ a, const float* __restrict__ b,
    const float* __restrict__ gam, const float* __restrict__ bet,
    float* __restrict__ out,
    __nv_bfloat16* __restrict__ oh, __nv_bfloat16* __restrict__ ol,
    int do_split)
{
    __shared__ float red[8];
    __shared__ float s_mu, s_rstd;
    const int tid = threadIdx.x;
    const int lane = tid & 31, w = tid >> 5;
    size_t idx = (size_t)blockIdx.x * 256 + tid;
    float v = a[idx] + b[idx];

    float s = v;
#pragma unroll
    for (int o = 16; o; o >>= 1) s += __shfl_xor_sync(0xffffffffu, s, o);
    if (lane == 0) red[w] = s;
    __syncthreads();
    if (tid == 0) {
        float t = 0.f;
        for (int i = 0; i < 8; i++) t += red[i];
        s_mu = t * (1.f / 256.f);
    }
    __syncthreads();
    float d = v - s_mu;
    float sq = d * d;
    __syncthreads();
#pragma unroll
    for (int o = 16; o; o >>= 1) sq += __shfl_xor_sync(0xffffffffu, sq, o);
    if (lane == 0) red[w] = sq;
    __syncthreads();
    if (tid == 0) {
        float t = 0.f;
        for (int i = 0; i < 8; i++) t += red[i];
        s_rstd = rsqrtf(t * (1.f / 256.f) + 1e-5f);
    }
    __syncthreads();
    float r = d * s_rstd * gam[tid] + bet[tid];
    out[idx] = r;
    if (do_split) {
        uint16_t hh, ll;
        cvt_split(r, hh, ll);
        *(uint16_t*)(oh + idx) = hh;
        *(uint16_t*)(ol + idx) = ll;
    }
}

// ---------------------------------------------------------------------------
// deform_attn: projections precomputed by GEMM; sigmoid/softmax + gather.
// ---------------------------------------------------------------------------
__global__ __launch_bounds__(256) void deform_attn(
    const float* __restrict__ dproj, const float* __restrict__ val,
    const int* __restrict__ pH, const int* __restrict__ pW,
    __nv_bfloat16* __restrict__ oh, __nv_bfloat16* __restrict__ ol)
{
    __shared__ float sref[2];
    __shared__ float soffs[64];
    __shared__ float sattw[32];
    const int bq = blockIdx.x;
    const int b = bq / QLEN;
    const int tid = threadIdx.x;

    if (tid < 98) {
        float v = dproj[(size_t)bq * 128 + tid];
        if (tid < 2)       sref[tid] = 1.f / (1.f + __expf(-v));
        else if (tid < 66) soffs[tid - 2] = v;
        else               sattw[tid - 66] = v;
    }
    __syncthreads();

    if (tid < 8) {
        float m = -3.4e38f;
#pragma unroll
        for (int p = 0; p < 4; p++) m = fmaxf(m, sattw[tid * 4 + p]);
        float e[4], s = 0.f;
#pragma unroll
        for (int p = 0; p < 4; p++) { e[p] = __expf(sattw[tid * 4 + p] - m); s += e[p]; }
        float inv = 1.f / s;
#pragma unroll
        for (int p = 0; p < 4; p++) sattw[tid * 4 + p] = e[p] * inv;
    }
    __syncthreads();

    const int H = *pH, W = *pW;
    const float fH = (float)H, fW = (float)W;
    const int h = tid >> 5, d = tid & 31;
    const float refx = sref[0], refy = sref[1];
    const float* vbase = val + (size_t)b * H * W * 256 + h * 32 + d;
    float acc = 0.f;
#pragma unroll
    for (int p = 0; p < NPTS; p++) {
        float locx = refx + soffs[h * 8 + 2 * p]     / fW;
        float locy = refy + soffs[h * 8 + 2 * p + 1] / fH;
        float xx = locx * fW - 0.5f;
        float yy = locy * fH - 0.5f;
        float x0f = floorf(xx), y0f = floorf(yy);
        int x0 = (int)x0f, y0 = (int)y0f;
        float lx = xx - x0f, ly = yy - y0f;
        float w00 = (1.f - lx) * (1.f - ly);
        float w10 = lx * (1.f - ly);
        float w01 = (1.f - lx) * ly;
        float w11 = lx * ly;
        float s = 0.f;
        bool vx0 = (x0 >= 0) & (x0 < W);
        bool vx1 = (x0 + 1 >= 0) & (x0 + 1 < W);
        bool vy0 = (y0 >= 0) & (y0 < H);
        bool vy1 = (y0 + 1 >= 0) & (y0 + 1 < H);
        if (vx0 & vy0) s += w00 * vbase[((size_t)y0 * W + x0) * 256];
        if (vx1 & vy0) s += w10 * vbase[((size_t)y0 * W + x0 + 1) * 256];
        if (vx0 & vy1) s += w01 * vbase[((size_t)(y0 + 1) * W + x0) * 256];
        if (vx1 & vy1) s += w11 * vbase[((size_t)(y0 + 1) * W + x0 + 1) * 256];
        acc += sattw[h * 4 + p] * s;
    }
    uint16_t hh, ll;
    cvt_split(acc, hh, ll);
    *(uint16_t*)(oh + (size_t)bq * 256 + tid) = hh;
    *(uint16_t*)(ol + (size_t)bq * 256 + tid) = ll;
}

// ---------------------------------------------------------------------------
extern "C" void kernel_launch(void* const* d_in, const int* in_sizes, int n_in,
                              void* d_out, int out_size)
{
    const float* tgt  = (const float*)d_in[0];
    const float* mem  = (const float*)d_in[1];
    const int*   pH   = (const int*)d_in[2];
    const int*   pW   = (const int*)d_in[3];
    const float* inw  = (const float*)d_in[4];
    const float* inb  = (const float*)d_in[5];
    const float* outw = (const float*)d_in[6];
    const float* outb = (const float*)d_in[7];
    const float* n1s  = (const float*)d_in[8];
    const float* n1b  = (const float*)d_in[9];
    const float* n2s  = (const float*)d_in[10];
    const float* n2b  = (const float*)d_in[11];
    const float* n3s  = (const float*)d_in[12];
    const float* n3b  = (const float*)d_in[13];
    const float* vpw  = (const float*)d_in[14];
    const float* vpb  = (const float*)d_in[15];
    const float* ofw  = (const float*)d_in[16];
    const float* ofb  = (const float*)d_in[17];
    const float* aww  = (const float*)d_in[18];
    const float* awb  = (const float*)d_in[19];
    const float* rfw  = (const float*)d_in[20];
    const float* rfb  = (const float*)d_in[21];
    const float* cow  = (const float*)d_in[22];
    const float* cob  = (const float*)d_in[23];
    const float* f1w  = (const float*)d_in[24];
    const float* f1b  = (const float*)d_in[25];
    const float* f2w  = (const float*)d_in[26];
    const float* f2b  = (const float*)d_in[27];
    float* outp = (float*)d_out;

    const int M  = in_sizes[0] / DM;          // 7200
    const int Mm = in_sizes[1] / DM;          // 80000
    const int B  = M / QLEN;                  // 8
    const int BHgrid = B * NH;                // 64

    float *t1, *val, *proj, *t2, *dproj, *dbias;
    __nv_bfloat16 *ah, *al, *bh, *bl, *wh, *wl, *ch, *cl, *fh, *fl;
    cudaGetSymbolAddress((void**)&t1,    g_t1);
    cudaGetSymbolAddress((void**)&val,   g_val);
    cudaGetSymbolAddress((void**)&proj,  g_proj);
    cudaGetSymbolAddress((void**)&t2,    g_t2);
    cudaGetSymbolAddress((void**)&dproj, g_dproj);
    cudaGetSymbolAddress((void**)&dbias, g_dbias);
    cudaGetSymbolAddress((void**)&ah,    g_ah);
    cudaGetSymbolAddress((void**)&al,    g_al);
    cudaGetSymbolAddress((void**)&bh,    g_bh);
    cudaGetSymbolAddress((void**)&bl,    g_bl);
    cudaGetSymbolAddress((void**)&wh,    g_wh);
    cudaGetSymbolAddress((void**)&wl,    g_wl);
    cudaGetSymbolAddress((void**)&ch,    g_ch);
    cudaGetSymbolAddress((void**)&cl,    g_cl);
    cudaGetSymbolAddress((void**)&fh,    g_fh);
    cudaGetSymbolAddress((void**)&fl,    g_fl);

    cudaFuncSetAttribute(hgemm, cudaFuncAttributeMaxDynamicSharedMemorySize, HG_SMEM);

    static cudaStream_t s2 = 0;
    static cudaEvent_t evFork = 0, evVal = 0;
    if (!s2) {
        cudaStreamCreateWithFlags(&s2, cudaStreamNonBlocking);
        cudaEventCreateWithFlags(&evFork, cudaEventDisableTiming);
        cudaEventCreateWithFlags(&evVal, cudaEventDisableTiming);
    }

    const int mb  = (M + 127) / 128;          // 57
    const int mmb = (Mm + 127) / 128;         // 625

    const int O_VPW = 0, O_INW = 65536, O_OUTW = 262144, O_COW = 327680,
              O_F1W = 393216, O_F2W = 655360;

    // ---- one-time prep (main) ----
    split_weights<<<224, 256>>>(vpw, inw, outw, cow, f1w, f2w, wh, wl);
    build_dproj_w<<<128, 256>>>(rfw, rfb, ofw, ofb, aww, awb, ch, cl, dbias);

    // ---- fork branch A: memory value projection on s2 ----
    cudaEventRecord(evFork, 0);
    cudaStreamWaitEvent(s2, evFork, 0);
    split_bf16<<<(Mm * 32 + 255) / 256, 256, 0, s2>>>(mem, ah, al, Mm * 32);
    hgemm<<<dim3(2, mmb), 128, HG_SMEM, s2>>>(ah, al, wh + O_VPW, wl + O_VPW,
                                              vpb, val, 0, 0, Mm, 256, 256, 0);
    cudaEventRecord(evVal, s2);

    // ---- branch B: self-attention chain on main ----
    split_bf16<<<(M * 32 + 255) / 256, 256>>>(tgt, bh, bl, M * 32);
    hgemm<<<dim3(6, mb), 128, HG_SMEM>>>(bh, bl, wh + O_INW, wl + O_INW,
                                         inb, 0, fh, fl, M, 768, 256, 2);
    flash_mma<<<dim3((QLEN + 127) / 128, BHgrid), 256>>>(fh, fl, bh, bl);
    hgemm<<<dim3(2, mb), 128, HG_SMEM>>>(bh, bl, wh + O_OUTW, wl + O_OUTW,
                                         outb, proj, 0, 0, M, 256, 256, 0);
    add_ln<<<M, 256>>>(proj, tgt, n1s, n1b, t1, bh, bl, 1);

    // deform projections (independent of val)
    hgemm<<<dim3(1, mb), 128, HG_SMEM>>>(bh, bl, ch, cl, dbias, dproj, 0, 0,
                                         M, 128, 256, 0);

    // ---- join: deform sampling needs val ----
    cudaStreamWaitEvent(0, evVal, 0);
    deform_attn<<<M, 256>>>(dproj, val, pH, pW, bh, bl);
    hgemm<<<dim3(2, mb), 128, HG_SMEM>>>(bh, bl, wh + O_COW, wl + O_COW,
                                         cob, proj, 0, 0, M, 256, 256, 0);
    add_ln<<<M, 256>>>(proj, t1, n2s, n2b, t2, bh, bl, 1);

    // ---- FFN ----
    hgemm<<<dim3(8, mb), 128, HG_SMEM>>>(bh, bl, wh + O_F1W, wl + O_F1W,
                                         f1b, 0, fh, fl, M, FFD, 256, 3);
    hgemm<<<dim3(2, mb), 128, HG_SMEM>>>(fh, fl, wh + O_F2W, wl + O_F2W,
                                         f2b, proj, 0, 0, M, 256, FFD, 0);
    add_ln<<<M, 256>>>(proj, t2, n3s, n3b, outp, 0, 0, 0);
}

// round 17
// speedup vs baseline: 1.1377x; 1.1377x over previous
#include <cuda_runtime.h>
#include <cuda_fp16.h>
#include <math.h>
#include <stdint.h>

#define QLEN 900
#define DM   256
#define NH   8
#define HD   32
#define NPTS 4
#define FFD  1024

// ---------------- scratch (__device__ globals; allocation-free) ----------------
__device__ float g_t1[1843200];
__device__ float g_val[20480000];     // [B*HW, 256]
__device__ float g_proj[1843200];
__device__ float g_t2[1843200];
__device__ float g_dproj[921600];     // [B*Q, 128] deform projections
__device__ float g_dbias[128];
// fp16 buffers: activations split hi/lo, weights single
__device__ __half g_ah[20480000];   // branch A (memory) exclusive
__device__ __half g_al[20480000];
__device__ __half g_bh[1843200];    // branch B activations
__device__ __half g_bl[1843200];
__device__ __half g_wh[917504];     // all weights (single fp16)
__device__ __half g_ch[32768];      // deform proj weights 128x256
__device__ __half g_fh[7372800];    // qkv / ffn intermediate hi
__device__ __half g_fl[7372800];    // qkv / ffn intermediate lo

// ============================================================================
// helpers
// ============================================================================
__device__ __forceinline__ uint32_t smem_u32(const void* p) {
    uint32_t a;
    asm("{ .reg .u64 t; cvta.to.shared.u64 t, %1; cvt.u32.u64 %0, t; }"
        : "=r"(a) : "l"(p));
    return a;
}
__device__ __forceinline__ uint32_t sw64(uint32_t off) {
    return off ^ ((off >> 3) & 0x30);
}
__device__ __forceinline__ void cvt_splith(float f, uint16_t& h, uint16_t& l) {
    __half hb = __float2half_rn(f);
    float r = f - __half2float(hb);
    __half lb = __float2half_rn(r);
    h = *reinterpret_cast<uint16_t*>(&hb);
    l = *reinterpret_cast<uint16_t*>(&lb);
}
__device__ __forceinline__ uint16_t cvt_h(float f) {
    __half hb = __float2half_rn(f);
    return *reinterpret_cast<uint16_t*>(&hb);
}
__device__ __forceinline__ void ldmx4(uint32_t* r, uint32_t addr) {
    asm volatile("ldmatrix.sync.aligned.m8n8.x4.shared.b16 {%0,%1,%2,%3}, [%4];"
        : "=r"(r[0]), "=r"(r[1]), "=r"(r[2]), "=r"(r[3]) : "r"(addr));
}
__device__ __forceinline__ void ldmx4t(uint32_t* r, uint32_t addr) {
    asm volatile("ldmatrix.sync.aligned.m8n8.x4.trans.shared.b16 {%0,%1,%2,%3}, [%4];"
        : "=r"(r[0]), "=r"(r[1]), "=r"(r[2]), "=r"(r[3]) : "r"(addr));
}
__device__ __forceinline__ void mma16816(float* d, const uint32_t* a,
                                         uint32_t b0, uint32_t b1) {
    asm volatile(
        "mma.sync.aligned.m16n8k16.row.col.f32.f16.f16.f32 "
        "{%0,%1,%2,%3}, {%4,%5,%6,%7}, {%8,%9}, {%0,%1,%2,%3};"
        : "+f"(d[0]), "+f"(d[1]), "+f"(d[2]), "+f"(d[3])
        : "r"(a[0]), "r"(a[1]), "r"(a[2]), "r"(a[3]), "r"(b0), "r"(b1));
}
__device__ __forceinline__ void cp_async16(uint32_t dst, const void* src, uint32_t sz) {
    asm volatile("cp.async.cg.shared.global [%0], [%1], 16, %2;"
        :: "r"(dst), "l"(src), "r"(sz));
}
#define CP_COMMIT() asm volatile("cp.async.commit_group;" ::: "memory")
#define CP_WAIT0()  asm volatile("cp.async.wait_group 0;" ::: "memory")
#define CP_WAIT1()  asm volatile("cp.async.wait_group 1;" ::: "memory")

// ============================================================================
// split_f16: fp32 -> (hi, lo) fp16; 8 elems (2 float4 in, uint4 out) / thread.
// ============================================================================
__global__ __launch_bounds__(256) void split_f16(
    const float* __restrict__ x, __half* __restrict__ hi,
    __half* __restrict__ lo, int n8)
{
    int i = blockIdx.x * 256 + threadIdx.x;
    if (i >= n8) return;
    float4 v0 = ((const float4*)x)[2 * i];
    float4 v1 = ((const float4*)x)[2 * i + 1];
    uint16_t h[8], l[8];
    cvt_splith(v0.x, h[0], l[0]); cvt_splith(v0.y, h[1], l[1]);
    cvt_splith(v0.z, h[2], l[2]); cvt_splith(v0.w, h[3], l[3]);
    cvt_splith(v1.x, h[4], l[4]); cvt_splith(v1.y, h[5], l[5]);
    cvt_splith(v1.z, h[6], l[6]); cvt_splith(v1.w, h[7], l[7]);
    ((uint4*)hi)[i] = make_uint4(
        (uint32_t)h[0] | ((uint32_t)h[1] << 16), (uint32_t)h[2] | ((uint32_t)h[3] << 16),
        (uint32_t)h[4] | ((uint32_t)h[5] << 16), (uint32_t)h[6] | ((uint32_t)h[7] << 16));
    ((uint4*)lo)[i] = make_uint4(
        (uint32_t)l[0] | ((uint32_t)l[1] << 16), (uint32_t)l[2] | ((uint32_t)l[3] << 16),
        (uint32_t)l[4] | ((uint32_t)l[5] << 16), (uint32_t)l[6] | ((uint32_t)l[7] << 16));
}

// ============================================================================
// split_weights: all 6 weight matrices -> one concatenated fp16 buffer.
// ============================================================================
__global__ __launch_bounds__(256) void split_weights(
    const float* __restrict__ vpw, const float* __restrict__ inw,
    const float* __restrict__ outw, const float* __restrict__ cow,
    const float* __restrict__ f1w, const float* __restrict__ f2w,
    __half* __restrict__ wh)
{
    int i0 = blockIdx.x * 1024 + threadIdx.x;
#pragma unroll
    for (int it = 0; it < 4; it++) {
        int i = i0 + it * 256;
        if (i >= 229376) return;
        const float* src; int li;
        if (i < 16384)       { src = vpw;  li = i; }
        else if (i < 65536)  { src = inw;  li = i - 16384; }
        else if (i < 81920)  { src = outw; li = i - 65536; }
        else if (i < 98304)  { src = cow;  li = i - 81920; }
        else if (i < 163840) { src = f1w;  li = i - 98304; }
        else                 { src = f2w;  li = i - 163840; }
        float4 v = ((const float4*)src)[li];
        uint16_t h0 = cvt_h(v.x), h1 = cvt_h(v.y), h2 = cvt_h(v.z), h3 = cvt_h(v.w);
        ((uint2*)wh)[i] = make_uint2((uint32_t)h0 | ((uint32_t)h1 << 16),
                                     (uint32_t)h2 | ((uint32_t)h3 << 16));
    }
}

// ============================================================================
// build_dproj_w: concat [ref(2) | offs(64) | attw(32) | pad(30)] x 256 weights
// ============================================================================
__global__ __launch_bounds__(256) void build_dproj_w(
    const float* __restrict__ rfw, const float* __restrict__ rfb,
    const float* __restrict__ ofw, const float* __restrict__ ofb,
    const float* __restrict__ aww, const float* __restrict__ awb,
    __half* __restrict__ ch, float* __restrict__ dbias)
{
    int row = blockIdx.x, tid = threadIdx.x;
    float v = 0.f;
    if (row < 2)       v = rfw[row * 256 + tid];
    else if (row < 66) v = ofw[(row - 2) * 256 + tid];
    else if (row < 98) v = aww[(row - 66) * 256 + tid];
    *(uint16_t*)(ch + row * 256 + tid) = cvt_h(v);
    if (tid == 0)
        dbias[row] = row < 2 ? rfb[row] : row < 66 ? ofb[row - 2]
                   : row < 98 ? awb[row - 66] : 0.f;
}

// ============================================================================
// hgemm: C = act(A @ W^T + bias), fp16 asymmetric: A split hi/lo, W single.
// D = Ah*W + Al*W (2 MMA passes). 4 warps, 2x2 warp grid of 64x64 sub-tiles.
// BK=32, 2-stage cp.async, 48KB smem (Ah@0 Al@8192 W@16384 per 24576B stage).
// mode bit0=relu, bit1=split-output (fp16 Ch/Cl).
// ============================================================================
#define HG_SMEM (2 * 24576)

__global__ __launch_bounds__(128, 2) void hgemm(
    const __half* __restrict__ Ah, const __half* __restrict__ Al,
    const __half* __restrict__ Wh,
    const float* __restrict__ bias, float* __restrict__ C,
    __half* __restrict__ Ch, __half* __restrict__ Cl,
    int M, int N, int K, int mode)
{
    extern __shared__ char sm[];
    const uint32_t sb = smem_u32(sm);
    const int tid = threadIdx.x;
    const int wid = tid >> 5, lane = tid & 31;
    const int row0 = blockIdx.y * 128, col0 = blockIdx.x * 128;
    const int wm = (wid & 1) * 64;
    const int wn = (wid >> 1) * 64;

    float acc[4][8][4];
#pragma unroll
    for (int mt = 0; mt < 4; mt++)
#pragma unroll
        for (int nt = 0; nt < 8; nt++)
#pragma unroll
            for (int j = 0; j < 4; j++) acc[mt][nt][j] = 0.f;

    const uint32_t a_row = wm + (lane & 15);
    const uint32_t a_cb  = (lane >> 4) * 16;
    const uint32_t b_rowb = wn + (lane & 7) + ((lane >> 4) << 3);
    const uint32_t b_cb  = ((lane >> 3) & 1) * 16;
    const int nc = K >> 5;                 // chunks of 32

    auto load_chunk = [&](int c, uint32_t bufbase) {
        const int k0 = c << 5;
#pragma unroll
        for (int it = 0; it < 4; it++) {
            int slot = tid + it * 128;
            int r = slot >> 2;
            int le8 = (slot & 3) * 8;
            uint32_t so = sw64((uint32_t)(r * 64 + le8 * 2));
            int ra = row0 + r < M ? row0 + r : M - 1;
            uint32_t asz = (row0 + r < M) ? 16u : 0u;
            cp_async16(bufbase + so,         Ah + (size_t)ra * K + k0 + le8, asz);
            cp_async16(bufbase + 8192 + so,  Al + (size_t)ra * K + k0 + le8, asz);
            cp_async16(bufbase + 16384 + so, Wh + (size_t)(col0 + r) * K + k0 + le8, 16u);
        }
    };

    load_chunk(0, sb);
    CP_COMMIT();

    for (int c = 0; c < nc; c++) {
        const uint32_t stb = sb + (uint32_t)(c & 1) * 24576;
        if (c + 1 < nc) {
            load_chunk(c + 1, sb + (uint32_t)((c + 1) & 1) * 24576);
            CP_COMMIT();
            CP_WAIT1();
        } else {
            CP_WAIT0();
        }
        __syncthreads();

#pragma unroll
        for (int ks = 0; ks < 32; ks += 16) {
            uint32_t ah[4][4], alr[4][4];
#pragma unroll
            for (int mt = 0; mt < 4; mt++) {
                uint32_t off = sw64((a_row + mt * 16) * 64 + ks * 2 + a_cb);
                ldmx4(ah[mt],  stb + off);
                ldmx4(alr[mt], stb + 8192 + off);
            }
#pragma unroll
            for (int jj = 0; jj < 4; jj++) {
                uint32_t off = sw64((b_rowb + jj * 16) * 64 + ks * 2 + b_cb);
                uint32_t bb[4];
                ldmx4(bb, stb + 16384 + off);
                // per-acc term order: ah*b -> al*b
#pragma unroll
                for (int mt = 0; mt < 4; mt++) {
                    mma16816(acc[mt][2*jj],   ah[mt], bb[0], bb[1]);
                    mma16816(acc[mt][2*jj+1], ah[mt], bb[2], bb[3]);
                }
#pragma unroll
                for (int mt = 0; mt < 4; mt++) {
                    mma16816(acc[mt][2*jj],   alr[mt], bb[0], bb[1]);
                    mma16816(acc[mt][2*jj+1], alr[mt], bb[2], bb[3]);
                }
            }
        }
        __syncthreads();
    }

    const bool relu = mode & 1;
    const bool split = mode & 2;
#pragma unroll
    for (int mt = 0; mt < 4; mt++) {
        int r0e = row0 + wm + mt * 16 + (lane >> 2);
#pragma unroll
        for (int nt = 0; nt < 8; nt++) {
            int c = col0 + wn + nt * 8 + (lane & 3) * 2;
            float b0 = bias[c], b1 = bias[c + 1];
            float2 v0 = make_float2(acc[mt][nt][0] + b0, acc[mt][nt][1] + b1);
            float2 v1 = make_float2(acc[mt][nt][2] + b0, acc[mt][nt][3] + b1);
            if (relu) {
                v0.x = fmaxf(v0.x, 0.f); v0.y = fmaxf(v0.y, 0.f);
                v1.x = fmaxf(v1.x, 0.f); v1.y = fmaxf(v1.y, 0.f);
            }
            if (!split) {
                if (r0e < M)     *(float2*)(C + (size_t)r0e * N + c) = v0;
                if (r0e + 8 < M) *(float2*)(C + (size_t)(r0e + 8) * N + c) = v1;
            } else {
                uint16_t h0,h1,l0,l1;
                if (r0e < M) {
                    cvt_splith(v0.x, h0, l0); cvt_splith(v0.y, h1, l1);
                    *(uint32_t*)(Ch + (size_t)r0e * N + c) =
                        (uint32_t)h0 | ((uint32_t)h1 << 16);
                    *(uint32_t*)(Cl + (size_t)r0e * N + c) =
                        (uint32_t)l0 | ((uint32_t)l1 << 16);
                }
                if (r0e + 8 < M) {
                    cvt_splith(v1.x, h0, l0); cvt_splith(v1.y, h1, l1);
                    *(uint32_t*)(Ch + (size_t)(r0e + 8) * N + c) =
                        (uint32_t)h0 | ((uint32_t)h1 << 16);
                    *(uint32_t*)(Cl + (size_t)(r0e + 8) * N + c) =
                        (uint32_t)l0 | ((uint32_t)l1 << 16);
                }
            }
        }
    }
}

// ============================================================================
// flash_mma: fused flash self-attention, fp16x3 (hi/lo both sides),
// 64-query tiles, 128 threads (R15 shape).
// ============================================================================
__global__ __launch_bounds__(128) void flash_mma(
    const __half* __restrict__ QKVh, const __half* __restrict__ QKVl,
    __half* __restrict__ Oh, __half* __restrict__ Ol)
{
    __shared__ __align__(16) char sQ[2][4096];       // [hi/lo] 64 rows x 64B
    __shared__ __align__(16) char sKV[2][4][4096];   // [stage][Kh,Kl,Vh,Vl]

    const int bh = blockIdx.y;
    const int b = bh >> 3, h = bh & 7;
    const int q0 = blockIdx.x * 64;
    const int tid = threadIdx.x;
    const int w = tid >> 5, lane = tid & 31;
    const float scale = 0.17677669529663687f;

    const size_t rowbase = (size_t)b * QLEN * 768 + h * 32;
    const __half* gqh = QKVh + rowbase;
    const __half* gql = QKVl + rowbase;

    const uint32_t uQ0 = smem_u32(sQ[0]), uQ1 = smem_u32(sQ[1]);
    const uint32_t uKV = smem_u32(sKV[0][0]);

    const int lrow = tid >> 1;
    const int lel  = (tid & 1) * 16;
    const uint32_t so0 = sw64((uint32_t)(lrow * 64 + lel * 2));
    const uint32_t so1 = sw64((uint32_t)(lrow * 64 + lel * 2 + 16));

    {
        uint32_t qsz = (q0 + lrow < QLEN) ? 16u : 0u;
        const __half* sh = gqh + (size_t)(q0 + lrow) * 768 + lel;
        const __half* sl = gql + (size_t)(q0 + lrow) * 768 + lel;
        cp_async16(uQ0 + so0, sh, qsz);     cp_async16(uQ0 + so1, sh + 8, qsz);
        cp_async16(uQ1 + so0, sl, qsz);     cp_async16(uQ1 + so1, sl + 8, qsz);
        uint32_t ksz = (lrow < QLEN) ? 16u : 0u;
        const __half* kh = gqh + 256 + (size_t)lrow * 768 + lel;
        const __half* kl = gql + 256 + (size_t)lrow * 768 + lel;
        const __half* vh = gqh + 512 + (size_t)lrow * 768 + lel;
        const __half* vl = gql + 512 + (size_t)lrow * 768 + lel;
        cp_async16(uKV + so0, kh, ksz);             cp_async16(uKV + so1, kh + 8, ksz);
        cp_async16(uKV + 4096 + so0, kl, ksz);      cp_async16(uKV + 4096 + so1, kl + 8, ksz);
        cp_async16(uKV + 8192 + so0, vh, ksz);      cp_async16(uKV + 8192 + so1, vh + 8, ksz);
        cp_async16(uKV + 12288 + so0, vl, ksz);     cp_async16(uKV + 12288 + so1, vl + 8, ksz);
        CP_COMMIT();
    }
    CP_WAIT0();
    __syncthreads();

    uint32_t qa[2][2][4];
#pragma unroll
    for (int ks = 0; ks < 2; ks++) {
        uint32_t off = sw64((uint32_t)((w*16 + (lane & 15)) * 64
                            + ks * 32 + (lane >> 4) * 16));
        ldmx4(qa[0][ks], uQ0 + off);
        ldmx4(qa[1][ks], uQ1 + off);
    }

    float m0 = -1e30f, m1 = -1e30f, l0s = 0.f, l1s = 0.f;
    float o[4][4];
#pragma unroll
    for (int i = 0; i < 4; i++)
#pragma unroll
        for (int j = 0; j < 4; j++) o[i][j] = 0.f;

    for (int kt = 0; kt < 15; kt++) {
        if (kt < 14) {
            const int k0n = (kt + 1) * 64;
            const uint32_t nb = uKV + (uint32_t)((kt + 1) & 1) * 16384;
            uint32_t ksz = (k0n + lrow < QLEN) ? 16u : 0u;
            const __half* kh = gqh + 256 + (size_t)(k0n + lrow) * 768 + lel;
            const __half* kl = gql + 256 + (size_t)(k0n + lrow) * 768 + lel;
            const __half* vh = gqh + 512 + (size_t)(k0n + lrow) * 768 + lel;
            const __half* vl = gql + 512 + (size_t)(k0n + lrow) * 768 + lel;
            cp_async16(nb + so0, kh, ksz);            cp_async16(nb + so1, kh + 8, ksz);
            cp_async16(nb + 4096 + so0, kl, ksz);     cp_async16(nb + 4096 + so1, kl + 8, ksz);
            cp_async16(nb + 8192 + so0, vh, ksz);     cp_async16(nb + 8192 + so1, vh + 8, ksz);
            cp_async16(nb + 12288 + so0, vl, ksz);    cp_async16(nb + 12288 + so1, vl + 8, ksz);
            CP_COMMIT();
        }

        const uint32_t stb = uKV + (uint32_t)(kt & 1) * 16384;
        const int k0 = kt * 64;

        float s[8][4];
#pragma unroll
        for (int i = 0; i < 8; i++)
#pragma unroll
            for (int j = 0; j < 4; j++) s[i][j] = 0.f;
#pragma unroll
        for (int ks = 0; ks < 2; ks++) {
            uint32_t bhh[4][4], bll[4][4];
#pragma unroll
            for (int jj = 0; jj < 4; jj++) {
                uint32_t off = sw64((uint32_t)((jj*16 + (lane & 7)
                               + ((lane >> 4) << 3)) * 64
                               + ((lane >> 3) & 1) * 16 + ks * 32));
                ldmx4(bhh[jj], stb + off);
                ldmx4(bll[jj], stb + 4096 + off);
            }
#pragma unroll
            for (int jj = 0; jj < 4; jj++) {
                mma16816(s[2*jj],   qa[0][ks], bhh[jj][0], bhh[jj][1]);
                mma16816(s[2*jj+1], qa[0][ks], bhh[jj][2], bhh[jj][3]);
            }
#pragma unroll
            for (int jj = 0; jj < 4; jj++) {
                mma16816(s[2*jj],   qa[0][ks], bll[jj][0], bll[jj][1]);
                mma16816(s[2*jj+1], qa[0][ks], bll[jj][2], bll[jj][3]);
            }
#pragma unroll
            for (int jj = 0; jj < 4; jj++) {
                mma16816(s[2*jj],   qa[1][ks], bhh[jj][0], bhh[jj][1]);
                mma16816(s[2*jj+1], qa[1][ks], bhh[jj][2], bhh[jj][3]);
            }
        }
#pragma unroll
        for (int jn = 0; jn < 8; jn++) {
#pragma unroll
            for (int j = 0; j < 4; j++) s[jn][j] *= scale;
        }
        const int colb = k0 + (lane & 3) * 2;
#pragma unroll
        for (int jn = 0; jn < 8; jn++) {
            int c0 = colb + jn * 8;
            if (c0 >= QLEN)     { s[jn][0] = -1e30f; s[jn][2] = -1e30f; }
            if (c0 + 1 >= QLEN) { s[jn][1] = -1e30f; s[jn][3] = -1e30f; }
        }

        float mx0 = -1e30f, mx1 = -1e30f;
#pragma unroll
        for (int jn = 0; jn < 8; jn++) {
            mx0 = fmaxf(mx0, fmaxf(s[jn][0], s[jn][1]));
            mx1 = fmaxf(mx1, fmaxf(s[jn][2], s[jn][3]));
        }
        mx0 = fmaxf(mx0, __shfl_xor_sync(0xffffffffu, mx0, 1));
        mx0 = fmaxf(mx0, __shfl_xor_sync(0xffffffffu, mx0, 2));
        mx1 = fmaxf(mx1, __shfl_xor_sync(0xffffffffu, mx1, 1));
        mx1 = fmaxf(mx1, __shfl_xor_sync(0xffffffffu, mx1, 2));
        float mn0 = fmaxf(m0, mx0), mn1 = fmaxf(m1, mx1);
        float corr0 = __expf(m0 - mn0), corr1 = __expf(m1 - mn1);
        m0 = mn0; m1 = mn1;
        float rs0 = 0.f, rs1 = 0.f;
#pragma unroll
        for (int jn = 0; jn < 8; jn++) {
            s[jn][0] = __expf(s[jn][0] - mn0);
            s[jn][1] = __expf(s[jn][1] - mn0);
            s[jn][2] = __expf(s[jn][2] - mn1);
            s[jn][3] = __expf(s[jn][3] - mn1);
            rs0 += s[jn][0] + s[jn][1];
            rs1 += s[jn][2] + s[jn][3];
        }
        rs0 += __shfl_xor_sync(0xffffffffu, rs0, 1);
        rs0 += __shfl_xor_sync(0xffffffffu, rs0, 2);
        rs1 += __shfl_xor_sync(0xffffffffu, rs1, 1);
        rs1 += __shfl_xor_sync(0xffffffffu, rs1, 2);
        l0s = l0s * corr0 + rs0;
        l1s = l1s * corr1 + rs1;
#pragma unroll
        for (int jn = 0; jn < 4; jn++) {
            o[jn][0] *= corr0; o[jn][1] *= corr0;
            o[jn][2] *= corr1; o[jn][3] *= corr1;
        }

#pragma unroll
        for (int ks = 0; ks < 4; ks++) {
            uint32_t pah[4], pal[4];
            {
                const float* t0 = s[2*ks];
                const float* t1 = s[2*ks+1];
                uint16_t h0,h1,l0,l1;
                cvt_splith(t0[0],h0,l0); cvt_splith(t0[1],h1,l1);
                pah[0] = (uint32_t)h0 | ((uint32_t)h1<<16);
                pal[0] = (uint32_t)l0 | ((uint32_t)l1<<16);
                cvt_splith(t0[2],h0,l0); cvt_splith(t0[3],h1,l1);
                pah[1] = (uint32_t)h0 | ((uint32_t)h1<<16);
                pal[1] = (uint32_t)l0 | ((uint32_t)l1<<16);
                cvt_splith(t1[0],h0,l0); cvt_splith(t1[1],h1,l1);
                pah[2] = (uint32_t)h0 | ((uint32_t)h1<<16);
                pal[2] = (uint32_t)l0 | ((uint32_t)l1<<16);
                cvt_splith(t1[2],h0,l0); cvt_splith(t1[3],h1,l1);
                pah[3] = (uint32_t)h0 | ((uint32_t)h1<<16);
                pal[3] = (uint32_t)l0 | ((uint32_t)l1<<16);
            }
            uint32_t vrow = (uint32_t)(ks * 16 + (lane & 7) + ((lane >> 3) & 1) * 8);
            uint32_t vhh[2][4], vll[2][4];
#pragma unroll
            for (int jj = 0; jj < 2; jj++) {
                uint32_t off = sw64(vrow * 64 + jj * 32 + (lane >> 4) * 16);
                ldmx4t(vhh[jj], stb + 8192 + off);
                ldmx4t(vll[jj], stb + 12288 + off);
            }
#pragma unroll
            for (int jj = 0; jj < 2; jj++) {
                mma16816(o[2*jj],   pah, vhh[jj][0], vhh[jj][1]);
                mma16816(o[2*jj+1], pah, vhh[jj][2], vhh[jj][3]);
            }
#pragma unroll
            for (int jj = 0; jj < 2; jj++) {
                mma16816(o[2*jj],   pah, vll[jj][0], vll[jj][1]);
                mma16816(o[2*jj+1], pah, vll[jj][2], vll[jj][3]);
            }
#pragma unroll
            for (int jj = 0; jj < 2; jj++) {
                mma16816(o[2*jj],   pal, vhh[jj][0], vhh[jj][1]);
                mma16816(o[2*jj+1], pal, vhh[jj][2], vhh[jj][3]);
            }
        }

        if (kt < 14) CP_WAIT0();
        __syncthreads();
    }

    {
        int r0 = q0 + w * 16 + (lane >> 2);
        float i0 = 1.f / l0s, i1 = 1.f / l1s;
#pragma unroll
        for (int jn = 0; jn < 4; jn++) {
            int c = h * 32 + jn * 8 + (lane & 3) * 2;
            uint16_t h0,h1,l0,l1;
            if (r0 < QLEN) {
                cvt_splith(o[jn][0] * i0, h0, l0);
                cvt_splith(o[jn][1] * i0, h1, l1);
                size_t off = (size_t)(b * QLEN + r0) * 256 + c;
                *(uint32_t*)(Oh + off) = (uint32_t)h0 | ((uint32_t)h1 << 16);
                *(uint32_t*)(Ol + off) = (uint32_t)l0 | ((uint32_t)l1 << 16);
            }
            if (r0 + 8 < QLEN) {
                cvt_splith(o[jn][2] * i1, h0, l0);
                cvt_splith(o[jn][3] * i1, h1, l1);
                size_t off = (size_t)(b * QLEN + r0 + 8) * 256 + c;
                *(uint32_t*)(Oh + off) = (uint32_t)h0 | ((uint32_t)h1 << 16);
                *(uint32_t*)(Ol + off) = (uint32_t)l0 | ((uint32_t)l1 << 16);
            }
        }
    }
}

// ---------------------------------------------------------------------------
// out = LayerNorm(a + b); optionally also emits fp16 hi/lo split of out.
// ---------------------------------------------------------------------------
__global__ __launch_bounds__(256) void add_ln(
    const float* __restrict__ a, const float* __restrict__ b,
    const float* __restrict__ gam, const float* __restrict__ bet,
    float* __restrict__ out,
    __half* __restrict__ oh, __half* __restrict__ ol,
    int do_split)
{
    __shared__ float red[8];
    __shared__ float s_mu, s_rstd;
    const int tid = threadIdx.x;
    const int lane = tid & 31, w = tid >> 5;
    size_t idx = (size_t)blockIdx.x * 256 + tid;
    float v = a[idx] + b[idx];

    float s = v;
#pragma unroll
    for (int o = 16; o; o >>= 1) s += __shfl_xor_sync(0xffffffffu, s, o);
    if (lane == 0) red[w] = s;
    __syncthreads();
    if (tid == 0) {
        float t = 0.f;
        for (int i = 0; i < 8; i++) t += red[i];
        s_mu = t * (1.f / 256.f);
    }
    __syncthreads();
    float d = v - s_mu;
    float sq = d * d;
    __syncthreads();
#pragma unroll
    for (int o = 16; o; o >>= 1) sq += __shfl_xor_sync(0xffffffffu, sq, o);
    if (lane == 0) red[w] = sq;
    __syncthreads();
    if (tid == 0) {
        float t = 0.f;
        for (int i = 0; i < 8; i++) t += red[i];
        s_rstd = rsqrtf(t * (1.f / 256.f) + 1e-5f);
    }
    __syncthreads();
    float r = d * s_rstd * gam[tid] + bet[tid];
    out[idx] = r;
    if (do_split) {
        uint16_t hh, ll;
        cvt_splith(r, hh, ll);
        *(uint16_t*)(oh + idx) = hh;
        *(uint16_t*)(ol + idx) = ll;
    }
}

// ---------------------------------------------------------------------------
// deform_attn: projections precomputed by GEMM; sigmoid/softmax + gather.
// ---------------------------------------------------------------------------
__global__ __launch_bounds__(256) void deform_attn(
    const float* __restrict__ dproj, const float* __restrict__ val,
    const int* __restrict__ pH, const int* __restrict__ pW,
    __half* __restrict__ oh, __half* __restrict__ ol)
{
    __shared__ float sref[2];
    __shared__ float soffs[64];
    __shared__ float sattw[32];
    const int bq = blockIdx.x;
    const int b = bq / QLEN;
    const int tid = threadIdx.x;

    if (tid < 98) {
        float v = dproj[(size_t)bq * 128 + tid];
        if (tid < 2)       sref[tid] = 1.f / (1.f + __expf(-v));
        else if (tid < 66) soffs[tid - 2] = v;
        else               sattw[tid - 66] = v;
    }
    __syncthreads();

    if (tid < 8) {
        float m = -3.4e38f;
#pragma unroll
        for (int p = 0; p < 4; p++) m = fmaxf(m, sattw[tid * 4 + p]);
        float e[4], s = 0.f;
#pragma unroll
        for (int p = 0; p < 4; p++) { e[p] = __expf(sattw[tid * 4 + p] - m); s += e[p]; }
        float inv = 1.f / s;
#pragma unroll
        for (int p = 0; p < 4; p++) sattw[tid * 4 + p] = e[p] * inv;
    }
    __syncthreads();

    const int H = *pH, W = *pW;
    const float fH = (float)H, fW = (float)W;
    const int h = tid >> 5, d = tid & 31;
    const float refx = sref[0], refy = sref[1];
    const float* vbase = val + (size_t)b * H * W * 256 + h * 32 + d;
    float acc = 0.f;
#pragma unroll
    for (int p = 0; p < NPTS; p++) {
        float locx = refx + soffs[h * 8 + 2 * p]     / fW;
        float locy = refy + soffs[h * 8 + 2 * p + 1] / fH;
        float xx = locx * fW - 0.5f;
        float yy = locy * fH - 0.5f;
        float x0f = floorf(xx), y0f = floorf(yy);
        int x0 = (int)x0f, y0 = (int)y0f;
        float lx = xx - x0f, ly = yy - y0f;
        float w00 = (1.f - lx) * (1.f - ly);
        float w10 = lx * (1.f - ly);
        float w01 = (1.f - lx) * ly;
        float w11 = lx * ly;
        float s = 0.f;
        bool vx0 = (x0 >= 0) & (x0 < W);
        bool vx1 = (x0 + 1 >= 0) & (x0 + 1 < W);
        bool vy0 = (y0 >= 0) & (y0 < H);
        bool vy1 = (y0 + 1 >= 0) & (y0 + 1 < H);
        if (vx0 & vy0) s += w00 * vbase[((size_t)y0 * W + x0) * 256];
        if (vx1 & vy0) s += w10 * vbase[((size_t)y0 * W + x0 + 1) * 256];
        if (vx0 & vy1) s += w01 * vbase[((size_t)(y0 + 1) * W + x0) * 256];
        if (vx1 & vy1) s += w11 * vbase[((size_t)(y0 + 1) * W + x0 + 1) * 256];
        acc += sattw[h * 4 + p] * s;
    }
    uint16_t hh, ll;
    cvt_splith(acc, hh, ll);
    *(uint16_t*)(oh + (size_t)bq * 256 + tid) = hh;
    *(uint16_t*)(ol + (size_t)bq * 256 + tid) = ll;
}

// ---------------------------------------------------------------------------
extern "C" void kernel_launch(void* const* d_in, const int* in_sizes, int n_in,
                              void* d_out, int out_size)
{
    const float* tgt  = (const float*)d_in[0];
    const float* mem  = (const float*)d_in[1];
    const int*   pH   = (const int*)d_in[2];
    const int*   pW   = (const int*)d_in[3];
    const float* inw  = (const float*)d_in[4];
    const float* inb  = (const float*)d_in[5];
    const float* outw = (const float*)d_in[6];
    const float* outb = (const float*)d_in[7];
    const float* n1s  = (const float*)d_in[8];
    const float* n1b  = (const float*)d_in[9];
    const float* n2s  = (const float*)d_in[10];
    const float* n2b  = (const float*)d_in[11];
    const float* n3s  = (const float*)d_in[12];
    const float* n3b  = (const float*)d_in[13];
    const float* vpw  = (const float*)d_in[14];
    const float* vpb  = (const float*)d_in[15];
    const float* ofw  = (const float*)d_in[16];
    const float* ofb  = (const float*)d_in[17];
    const float* aww  = (const float*)d_in[18];
    const float* awb  = (const float*)d_in[19];
    const float* rfw  = (const float*)d_in[20];
    const float* rfb  = (const float*)d_in[21];
    const float* cow  = (const float*)d_in[22];
    const float* cob  = (const float*)d_in[23];
    const float* f1w  = (const float*)d_in[24];
    const float* f1b  = (const float*)d_in[25];
    const float* f2w  = (const float*)d_in[26];
    const float* f2b  = (const float*)d_in[27];
    float* outp = (float*)d_out;

    const int M  = in_sizes[0] / DM;          // 7200
    const int Mm = in_sizes[1] / DM;          // 80000
    const int B  = M / QLEN;                  // 8
    const int BHgrid = B * NH;                // 64

    float *t1, *val, *proj, *t2, *dproj, *dbias;
    __half *ah, *al, *bh, *bl, *wh, *ch, *fh, *fl;
    cudaGetSymbolAddress((void**)&t1,    g_t1);
    cudaGetSymbolAddress((void**)&val,   g_val);
    cudaGetSymbolAddress((void**)&proj,  g_proj);
    cudaGetSymbolAddress((void**)&t2,    g_t2);
    cudaGetSymbolAddress((void**)&dproj, g_dproj);
    cudaGetSymbolAddress((void**)&dbias, g_dbias);
    cudaGetSymbolAddress((void**)&ah,    g_ah);
    cudaGetSymbolAddress((void**)&al,    g_al);
    cudaGetSymbolAddress((void**)&bh,    g_bh);
    cudaGetSymbolAddress((void**)&bl,    g_bl);
    cudaGetSymbolAddress((void**)&wh,    g_wh);
    cudaGetSymbolAddress((void**)&ch,    g_ch);
    cudaGetSymbolAddress((void**)&fh,    g_fh);
    cudaGetSymbolAddress((void**)&fl,    g_fl);

    cudaFuncSetAttribute(hgemm, cudaFuncAttributeMaxDynamicSharedMemorySize, HG_SMEM);

    static cudaStream_t s2 = 0;
    static cudaEvent_t evFork = 0, evVal = 0;
    if (!s2) {
        cudaStreamCreateWithFlags(&s2, cudaStreamNonBlocking);
        cudaEventCreateWithFlags(&evFork, cudaEventDisableTiming);
        cudaEventCreateWithFlags(&evVal, cudaEventDisableTiming);
    }

    const int mb  = (M + 127) / 128;          // 57
    const int mmb = (Mm + 127) / 128;         // 625

    const int O_VPW = 0, O_INW = 65536, O_OUTW = 262144, O_COW = 327680,
              O_F1W = 393216, O_F2W = 655360;

    // ---- one-time prep (main) ----
    split_weights<<<224, 256>>>(vpw, inw, outw, cow, f1w, f2w, wh);
    build_dproj_w<<<128, 256>>>(rfw, rfb, ofw, ofb, aww, awb, ch, dbias);

    // ---- fork branch A: memory value projection on s2 ----
    cudaEventRecord(evFork, 0);
    cudaStreamWaitEvent(s2, evFork, 0);
    split_f16<<<(Mm * 32 + 255) / 256, 256, 0, s2>>>(mem, ah, al, Mm * 32);
    hgemm<<<dim3(2, mmb), 128, HG_SMEM, s2>>>(ah, al, wh + O_VPW,
                                              vpb, val, 0, 0, Mm, 256, 256, 0);
    cudaEventRecord(evVal, s2);

    // ---- branch B: self-attention chain on main ----
    split_f16<<<(M * 32 + 255) / 256, 256>>>(tgt, bh, bl, M * 32);
    hgemm<<<dim3(6, mb), 128, HG_SMEM>>>(bh, bl, wh + O_INW,
                                         inb, 0, fh, fl, M, 768, 256, 2);
    flash_mma<<<dim3(15, BHgrid), 128>>>(fh, fl, bh, bl);
    hgemm<<<dim3(2, mb), 128, HG_SMEM>>>(bh, bl, wh + O_OUTW,
                                         outb, proj, 0, 0, M, 256, 256, 0);
    add_ln<<<M, 256>>>(proj, tgt, n1s, n1b, t1, bh, bl, 1);

    // deform projections (independent of val)
    hgemm<<<dim3(1, mb), 128, HG_SMEM>>>(bh, bl, ch, dbias, dproj, 0, 0,
                                         M, 128, 256, 0);

    // ---- join: deform sampling needs val ----
    cudaStreamWaitEvent(0, evVal, 0);
    deform_attn<<<M, 256>>>(dproj, val, pH, pW, bh, bl);
    hgemm<<<dim3(2, mb), 128, HG_SMEM>>>(bh, bl, wh + O_COW,
                                         cob, proj, 0, 0, M, 256, 256, 0);
    add_ln<<<M, 256>>>(proj, t1, n2s, n2b, t2, bh, bl, 1);

    // ---- FFN ----
    hgemm<<<dim3(8, mb), 128, HG_SMEM>>>(bh, bl, wh + O_F1W,
                                         f1b, 0, fh, fl, M, FFD, 256, 3);
    hgemm<<<dim3(2, mb), 128, HG_SMEM>>>(fh, fl, wh + O_F2W,
                                         f2b, proj, 0, 0, M, 256, FFD, 0);
    add_ln<<<M, 256>>>(proj, t2, n3s, n3b, outp, 0, 0, 0);
}